// round 3
// baseline (speedup 1.0000x reference)
#include <cuda_runtime.h>
#include <cstdint>

#define SEQ   8192
#define DIM   256
#define HID   1024
#define KCB   512
#define NCLS  50
#define NCTA  128
#define TPB   256
#define UPC   8        // hidden units per CTA = HID / NCTA

// ---------------- device-global scratch (no allocations allowed) -------------
__device__ int      g_idx[SEQ];
__device__ float    g_h[2][HID];
__device__ unsigned g_arrive = 0;
__device__ unsigned g_gen    = 0;

// ---------------- accurate-enough activations (fast-math independent) --------
__device__ __forceinline__ float sigm(float x) {
    return 1.0f / (1.0f + __expf(-x));
}
__device__ __forceinline__ float tanh_acc(float x) {
    float t = __expf(-2.0f * fabsf(x));       // t in (0,1], no overflow
    float r = (1.0f - t) / (1.0f + t);
    return copysignf(r, x);
}

// ======================= Kernel 1: VQ assignment =============================
// 256 CTAs x 256 threads. Each CTA handles 32 tokens; 8 threads per token
// sweep the 512 codes in shared-memory tiles. dist = ||c||^2 - 2 x.c
// (||x||^2 dropped: constant per token, argmin unaffected).
#define VQ_TOK  32
#define VQ_TILE 32
#define VQ_PAD  260   // 256 + 4 floats pad -> conflict-free strided rows
#define VQ_SMEM ((VQ_TOK * VQ_PAD + VQ_TILE * VQ_PAD) * sizeof(float))

__global__ __launch_bounds__(TPB)
void vq_kernel(const float* __restrict__ x, const float* __restrict__ cb) {
    extern __shared__ float sm[];
    float* sx  = sm;                     // [VQ_TOK][VQ_PAD]
    float* scb = sm + VQ_TOK * VQ_PAD;   // [VQ_TILE][VQ_PAD]
    __shared__ float scn[KCB];

    const int tid = threadIdx.x;
    const int t0  = blockIdx.x * VQ_TOK;

    // stage x tile (32 tokens x 256 dims)
    for (int i = tid; i < VQ_TOK * (DIM / 4); i += TPB) {
        int tt = i >> 6, d4 = i & 63;
        float4 v = *(const float4*)&x[(t0 + tt) * DIM + d4 * 4];
        *(float4*)&sx[tt * VQ_PAD + d4 * 4] = v;
    }
    // codebook squared norms
    for (int k = tid; k < KCB; k += TPB) {
        float s0 = 0.f, s1 = 0.f, s2 = 0.f, s3 = 0.f;
        const float4* cr = (const float4*)&cb[k * DIM];
        #pragma unroll 8
        for (int d = 0; d < DIM / 4; ++d) {
            float4 v = cr[d];
            s0 = fmaf(v.x, v.x, s0); s1 = fmaf(v.y, v.y, s1);
            s2 = fmaf(v.z, v.z, s2); s3 = fmaf(v.w, v.w, s3);
        }
        scn[k] = (s0 + s1) + (s2 + s3);
    }
    __syncthreads();

    const int tt = tid >> 3;   // token within CTA
    const int k0 = tid & 7;    // code-lane within token
    float best = 3.4e38f;
    int   bidx = 0;

    for (int tile = 0; tile < KCB / VQ_TILE; ++tile) {
        for (int i = tid; i < VQ_TILE * (DIM / 4); i += TPB) {
            int cc = i >> 6, d4 = i & 63;
            float4 v = *(const float4*)&cb[(tile * VQ_TILE + cc) * DIM + d4 * 4];
            *(float4*)&scb[cc * VQ_PAD + d4 * 4] = v;
        }
        __syncthreads();
        for (int c = k0; c < VQ_TILE; c += 8) {
            float a0 = 0.f, a1 = 0.f, a2 = 0.f, a3 = 0.f;
            const float* xr = &sx[tt * VQ_PAD];
            const float* cr = &scb[c * VQ_PAD];
            #pragma unroll
            for (int d = 0; d < DIM; d += 4) {
                float4 xv = *(const float4*)&xr[d];
                float4 cv = *(const float4*)&cr[d];
                a0 = fmaf(xv.x, cv.x, a0); a1 = fmaf(xv.y, cv.y, a1);
                a2 = fmaf(xv.z, cv.z, a2); a3 = fmaf(xv.w, cv.w, a3);
            }
            int   kk   = tile * VQ_TILE + c;
            float dist = scn[kk] - 2.0f * ((a0 + a1) + (a2 + a3));
            if (dist < best) { best = dist; bidx = kk; }   // k ascending -> first-min kept
        }
        __syncthreads();
    }
    // argmin across the 8 lanes of this token (width-8 segments)
    #pragma unroll
    for (int off = 4; off > 0; off >>= 1) {
        float ob = __shfl_down_sync(0xffffffffu, best, off, 8);
        int   oi = __shfl_down_sync(0xffffffffu, bidx, off, 8);
        if (ob < best || (ob == best && oi < bidx)) { best = ob; bidx = oi; }
    }
    if (k0 == 0) g_idx[t0 + tt] = bidx;
}

// ======================= Kernel 2: persistent LSTM ===========================
// 128 CTAs x 256 threads, all co-resident (reg-limited to 1 CTA/SM; 128 < 148).
// CTA b owns hidden units [b*8, b*8+8): 32 gate rows of W_hh kept in REGISTERS
// (128 fp32/thread). Per step: broadcast h via L2 (__ldcg), register-resident
// GEMV, width-8 shuffle reduce, gate nonlinearity, global sense barrier.
__device__ __forceinline__ void grid_barrier(int tid) {
    __syncthreads();
    if (tid == 0) {
        volatile unsigned* vgen = &g_gen;
        unsigned my = *vgen;
        __threadfence();
        if (atomicAdd(&g_arrive, 1u) == NCTA - 1) {
            atomicExch(&g_arrive, 0u);
            __threadfence();
            atomicAdd(&g_gen, 1u);
        } else {
            while (*vgen == my) { }
        }
        __threadfence();
    }
    __syncthreads();
}

__global__ __launch_bounds__(TPB, 1)
void lstm_kernel(const float* __restrict__ h0,   const float* __restrict__ c0,
                 const float* __restrict__ W_ih, const float* __restrict__ W_hh,
                 const float* __restrict__ b_ih, const float* __restrict__ b_hh)
{
    __shared__ float sh[HID];
    __shared__ float sg[32];
    __shared__ float sxc[32];
    __shared__ float sb[32];
    __shared__ int   s_idx;

    const int tid = threadIdx.x;
    const int b   = blockIdx.x;
    const int rg  = tid >> 3;                 // row-group 0..31 (gate*8 + unit)
    const int k   = tid & 7;                  // j-slice within row
    const int row = (rg >> 3) * HID + b * UPC + (rg & 7);

    // --- load this thread's W_hh slice into registers (one-time) ---
    float w[128];
    #pragma unroll
    for (int i = 0; i < 32; ++i) {
        float4 v = *(const float4*)&W_hh[row * HID + i * 32 + k * 4];
        w[4 * i + 0] = v.x; w[4 * i + 1] = v.y;
        w[4 * i + 2] = v.z; w[4 * i + 3] = v.w;
    }
    if (k == 0) sb[rg] = b_ih[row] + b_hh[row];

    float c_state = 0.0f;
    if (tid < UPC) c_state = c0[b * UPC + tid];

    for (int t = 0; t < SEQ; ++t) {
        // stage h into shared. MUST bypass L1 (__ldcg): g_h is re-written by
        // other CTAs between visits and L1 is not coherent.
        if (tid == 0) s_idx = g_idx[t];
        float4 hv4;
        if (t == 0) hv4 = *(const float4*)&h0[tid * 4];
        else        hv4 = __ldcg((const float4*)&g_h[t & 1][tid * 4]);
        *(float4*)&sh[tid * 4] = hv4;
        __syncthreads();

        // x-contribution gather: one W_ih element per gate row (L2-hot, 8 MB)
        if (tid < 32) {
            int grow = (tid >> 3) * HID + b * UPC + (tid & 7);
            sxc[tid] = __ldg(&W_ih[grow * KCB + s_idx]);
        }

        // register-resident partial GEMV, conflict-free strided h reads
        float a0 = 0.f, a1 = 0.f, a2 = 0.f, a3 = 0.f;
        #pragma unroll
        for (int i = 0; i < 32; ++i) {
            float4 hv = *(const float4*)&sh[i * 32 + k * 4];
            a0 = fmaf(w[4 * i + 0], hv.x, a0);
            a1 = fmaf(w[4 * i + 1], hv.y, a1);
            a2 = fmaf(w[4 * i + 2], hv.z, a2);
            a3 = fmaf(w[4 * i + 3], hv.w, a3);
        }
        float acc = (a0 + a1) + (a2 + a3);
        acc += __shfl_down_sync(0xffffffffu, acc, 4, 8);
        acc += __shfl_down_sync(0xffffffffu, acc, 2, 8);
        acc += __shfl_down_sync(0xffffffffu, acc, 1, 8);
        if (k == 0) sg[rg] = acc;
        __syncthreads();

        // gate nonlinearity + state update for this CTA's 8 units
        if (tid < UPC) {
            float gi = sg[tid]      + sxc[tid]      + sb[tid];
            float gf = sg[8 + tid]  + sxc[8 + tid]  + sb[8 + tid];
            float gg = sg[16 + tid] + sxc[16 + tid] + sb[16 + tid];
            float go = sg[24 + tid] + sxc[24 + tid] + sb[24 + tid];
            float iv = sigm(gi), fv = sigm(gf);
            float gv = tanh_acc(gg), ov = sigm(go);
            c_state = fv * c_state + iv * gv;
            __stcg(&g_h[(t + 1) & 1][b * UPC + tid], ov * tanh_acc(c_state));
        }
        grid_barrier(tid);
    }
}

// ======================= Kernel 3: classifier head ===========================
__global__ __launch_bounds__(256)
void out_kernel(const float* __restrict__ W_out, const float* __restrict__ b_out,
                float* __restrict__ out)
{
    __shared__ float sl[NCLS];
    __shared__ float s_lse;
    const int tid = threadIdx.x, wp = tid >> 5, lane = tid & 31;
    const float* h = g_h[0];   // SEQ even -> final h lands in buffer 0

    for (int l = wp; l < NCLS; l += 8) {
        float s = 0.0f;
        #pragma unroll 8
        for (int j = lane; j < HID; j += 32)
            s = fmaf(h[j], W_out[l * HID + j], s);
        #pragma unroll
        for (int off = 16; off > 0; off >>= 1)
            s += __shfl_down_sync(0xffffffffu, s, off);
        if (lane == 0) sl[l] = s + b_out[l];
    }
    __syncthreads();
    if (tid == 0) {
        float mx = -3.4e38f;
        for (int l = 0; l < NCLS; ++l) mx = fmaxf(mx, sl[l]);
        float se = 0.0f;
        for (int l = 0; l < NCLS; ++l) se += __expf(sl[l] - mx);
        s_lse = mx + __logf(se);
    }
    __syncthreads();
    if (tid < NCLS) out[tid] = sl[tid] - s_lse;
}

// ======================= launch ==============================================
extern "C" void kernel_launch(void* const* d_in, const int* in_sizes, int n_in,
                              void* d_out, int out_size) {
    const float* x     = (const float*)d_in[0];
    const float* h0    = (const float*)d_in[1];
    const float* c0    = (const float*)d_in[2];
    const float* cb    = (const float*)d_in[3];
    const float* W_ih  = (const float*)d_in[4];
    const float* W_hh  = (const float*)d_in[5];
    const float* b_ih  = (const float*)d_in[6];
    const float* b_hh  = (const float*)d_in[7];
    const float* W_out = (const float*)d_in[8];
    const float* b_out = (const float*)d_in[9];

    cudaFuncSetAttribute(vq_kernel, cudaFuncAttributeMaxDynamicSharedMemorySize,
                         (int)VQ_SMEM);

    vq_kernel<<<SEQ / VQ_TOK, TPB, VQ_SMEM>>>(x, cb);
    lstm_kernel<<<NCTA, TPB>>>(h0, c0, W_ih, W_hh, b_ih, b_hh);
    out_kernel<<<1, 256>>>(W_out, b_out, (float*)d_out);
}

// round 4
// speedup vs baseline: 2.4216x; 2.4216x over previous
#include <cuda_runtime.h>
#include <cstdint>

#define SEQ   8192
#define DIM   256
#define HID   1024
#define KCB   512
#define NCLS  50
#define NCTA  128
#define TPB   256
#define UPC   8        // hidden units per CTA = HID / NCTA

// ---------------- device-global scratch (no allocations allowed) -------------
__device__ int      g_idx[SEQ];
// h publish buffer: slot s holds h(s), one {f32 bits, gen tag} per unit. 67 MB.
__device__ uint2    g_hpub[(SEQ + 1) * HID];
// W_ih transposed+permuted: [k][cta*32 + r] where r = gate*8 + unit. 8 MB.
__device__ float    g_wih_t[KCB * 4 * HID];
__device__ unsigned g_run = 0;   // generation counter, bumped once per launch

// ---------------- accurate-enough activations (fast-math independent) --------
__device__ __forceinline__ float sigm(float x) {
    return 1.0f / (1.0f + __expf(-x));
}
__device__ __forceinline__ float tanh_acc(float x) {
    float t = __expf(-2.0f * fabsf(x));
    float r = (1.0f - t) / (1.0f + t);
    return copysignf(r, x);
}

// packed f32x2 FMA (PTX-only pattern; element-wise fp32 FMA on a 64-bit pair)
__device__ __forceinline__ void ffma2(unsigned long long& d,
                                      unsigned long long a,
                                      unsigned long long b) {
    asm("fma.rn.f32x2 %0, %1, %2, %0;" : "+l"(d) : "l"(a), "l"(b));
}

__device__ __forceinline__ uint4 ldcg_u4(const uint4* p) {
    uint4 v;
    asm volatile("ld.global.cg.v4.u32 {%0,%1,%2,%3}, [%4];"
                 : "=r"(v.x), "=r"(v.y), "=r"(v.z), "=r"(v.w)
                 : "l"(p) : "memory");
    return v;
}
__device__ __forceinline__ void stcg_u2(uint2* p, unsigned a, unsigned b) {
    asm volatile("st.global.cg.v2.u32 [%0], {%1,%2};"
                 :: "l"(p), "r"(a), "r"(b) : "memory");
}

// ======================= Kernel 1: VQ assignment (unchanged) =================
#define VQ_TOK  32
#define VQ_TILE 32
#define VQ_PAD  260
#define VQ_SMEM ((VQ_TOK * VQ_PAD + VQ_TILE * VQ_PAD) * sizeof(float))

__global__ __launch_bounds__(TPB)
void vq_kernel(const float* __restrict__ x, const float* __restrict__ cb) {
    extern __shared__ float sm[];
    float* sx  = sm;
    float* scb = sm + VQ_TOK * VQ_PAD;
    __shared__ float scn[KCB];

    const int tid = threadIdx.x;
    const int t0  = blockIdx.x * VQ_TOK;

    for (int i = tid; i < VQ_TOK * (DIM / 4); i += TPB) {
        int tt = i >> 6, d4 = i & 63;
        float4 v = *(const float4*)&x[(t0 + tt) * DIM + d4 * 4];
        *(float4*)&sx[tt * VQ_PAD + d4 * 4] = v;
    }
    for (int k = tid; k < KCB; k += TPB) {
        float s0 = 0.f, s1 = 0.f, s2 = 0.f, s3 = 0.f;
        const float4* cr = (const float4*)&cb[k * DIM];
        #pragma unroll 8
        for (int d = 0; d < DIM / 4; ++d) {
            float4 v = cr[d];
            s0 = fmaf(v.x, v.x, s0); s1 = fmaf(v.y, v.y, s1);
            s2 = fmaf(v.z, v.z, s2); s3 = fmaf(v.w, v.w, s3);
        }
        scn[k] = (s0 + s1) + (s2 + s3);
    }
    __syncthreads();

    const int tt = tid >> 3;
    const int k0 = tid & 7;
    float best = 3.4e38f;
    int   bidx = 0;

    for (int tile = 0; tile < KCB / VQ_TILE; ++tile) {
        for (int i = tid; i < VQ_TILE * (DIM / 4); i += TPB) {
            int cc = i >> 6, d4 = i & 63;
            float4 v = *(const float4*)&cb[(tile * VQ_TILE + cc) * DIM + d4 * 4];
            *(float4*)&scb[cc * VQ_PAD + d4 * 4] = v;
        }
        __syncthreads();
        for (int c = k0; c < VQ_TILE; c += 8) {
            float a0 = 0.f, a1 = 0.f, a2 = 0.f, a3 = 0.f;
            const float* xr = &sx[tt * VQ_PAD];
            const float* cr = &scb[c * VQ_PAD];
            #pragma unroll
            for (int d = 0; d < DIM; d += 4) {
                float4 xv = *(const float4*)&xr[d];
                float4 cv = *(const float4*)&cr[d];
                a0 = fmaf(xv.x, cv.x, a0); a1 = fmaf(xv.y, cv.y, a1);
                a2 = fmaf(xv.z, cv.z, a2); a3 = fmaf(xv.w, cv.w, a3);
            }
            int   kk   = tile * VQ_TILE + c;
            float dist = scn[kk] - 2.0f * ((a0 + a1) + (a2 + a3));
            if (dist < best) { best = dist; bidx = kk; }
        }
        __syncthreads();
    }
    #pragma unroll
    for (int off = 4; off > 0; off >>= 1) {
        float ob = __shfl_down_sync(0xffffffffu, best, off, 8);
        int   oi = __shfl_down_sync(0xffffffffu, bidx, off, 8);
        if (ob < best || (ob == best && oi < bidx)) { best = ob; bidx = oi; }
    }
    if (k0 == 0) g_idx[t0 + tt] = bidx;
}

// ======================= Kernel 1b: prep (W_ih transpose + gen bump) =========
// g_wih_t[k*4096 + cta*32 + r] = W_ih[rowg(r,cta)*512 + k], rowg = g*1024+cta*8+u.
__global__ __launch_bounds__(256)
void prep_kernel(const float* __restrict__ W_ih) {
    int gid = blockIdx.x * 256 + threadIdx.x;       // 0 .. 512*4096-1
    if (gid == 0) g_run = g_run + 1;
    int k = gid >> 12;
    int c = gid & 4095;
    int r = c & 31, cta = c >> 5;
    int rowg = (r >> 3) * HID + cta * UPC + (r & 7);
    g_wih_t[gid] = __ldg(&W_ih[rowg * KCB + k]);
}

// ======================= Kernel 2: persistent data-flow LSTM =================
// 128 CTAs x 256 threads (grid <= 148 SMs -> all co-resident, no deadlock).
// NO global barrier: h published as {value, gen} 8-byte words, consumers poll
// with L1-bypassing loads. Warp w owns gate-rows 4w..4w+3; lane l owns h slice
// [32l, 32l+32). Weights live in registers as f32x2 pairs.
#define SH_STRIDE 36   // 32 + 4 pad floats -> conflict-free lane-strided reads

__global__ __launch_bounds__(TPB, 1)
void lstm_kernel(const float* __restrict__ h0,   const float* __restrict__ c0,
                 const float* __restrict__ W_hh,
                 const float* __restrict__ b_ih, const float* __restrict__ b_hh)
{
    __shared__ float sh[32 * SH_STRIDE];
    __shared__ float sg[32];
    __shared__ float sxp[32];
    __shared__ float sbias[32];
    __shared__ int   s_idx[2];

    const int tid  = threadIdx.x;
    const int b    = blockIdx.x;
    const int w    = tid >> 5;                // warp 0..7 -> rows 4w..4w+3
    const int l    = tid & 31;                // lane -> h slice [32l, 32l+32)
    const unsigned gen = g_run;

    // --- one-time: weights into registers as packed f32x2 pairs --------------
    unsigned long long wp[4][16];
    #pragma unroll
    for (int p = 0; p < 4; ++p) {
        int r    = 4 * w + p;
        int rowg = (r >> 3) * HID + b * UPC + (r & 7);
        const ulonglong2* wr = (const ulonglong2*)&W_hh[rowg * HID + l * 32];
        #pragma unroll
        for (int q = 0; q < 8; ++q) {
            ulonglong2 v = wr[q];
            wp[p][2 * q]     = v.x;
            wp[p][2 * q + 1] = v.y;
        }
    }
    if (tid < 32) {
        int rowg = (tid >> 3) * HID + b * UPC + (tid & 7);
        sbias[tid] = b_ih[rowg] + b_hh[rowg];
    }
    float c_state = 0.0f;
    if (tid < UPC) c_state = c0[b * UPC + tid];
    if (tid == 0)  s_idx[0] = g_idx[0];
    __syncthreads();

    for (int step = 1; step <= SEQ; ++step) {
        // ---- issue x-path loads early (independent of the recurrence) -------
        float4 xw4;
        if (tid < 8) {
            int idx = s_idx[(step - 1) & 1];
            xw4 = *(const float4*)&g_wih_t[idx * (4 * HID) + b * 32 + tid * 4];
        }
        if (tid == 8 && step < SEQ) s_idx[step & 1] = __ldg(&g_idx[step]);

        // ---- acquire h(step-1): input at step 1, else poll tagged publishes -
        float4 hv;
        if (step == 1) {
            hv = *(const float4*)&h0[tid * 4];
        } else {
            const uint4* pa = (const uint4*)&g_hpub[(step - 1) * HID + tid * 4];
            uint4 A, B;
            for (;;) {
                A = ldcg_u4(pa);
                B = ldcg_u4(pa + 1);
                if (A.y == gen && A.w == gen && B.y == gen && B.w == gen) break;
            }
            hv.x = __uint_as_float(A.x); hv.y = __uint_as_float(A.z);
            hv.z = __uint_as_float(B.x); hv.w = __uint_as_float(B.z);
        }
        // stage: entries tid*4..+3 -> chunk tid>>3, offset (tid&7)*4
        *(float4*)&sh[(tid >> 3) * SH_STRIDE + (tid & 7) * 4] = hv;
        __syncthreads();

        // ---- register-resident GEMV: 4 rows x 32-wide slice, f32x2 FMAs -----
        unsigned long long acc[4] = {0ull, 0ull, 0ull, 0ull};
        const ulonglong2* hp = (const ulonglong2*)&sh[l * SH_STRIDE];
        #pragma unroll
        for (int q = 0; q < 8; ++q) {
            ulonglong2 h2 = hp[q];
            #pragma unroll
            for (int p = 0; p < 4; ++p) {
                ffma2(acc[p], wp[p][2 * q],     h2.x);
                ffma2(acc[p], wp[p][2 * q + 1], h2.y);
            }
        }
        float accf[4];
        #pragma unroll
        for (int p = 0; p < 4; ++p) {
            float lo, hi;
            asm("mov.b64 {%0,%1}, %2;" : "=f"(lo), "=f"(hi) : "l"(acc[p]));
            accf[p] = lo + hi;
        }
        #pragma unroll
        for (int off = 16; off > 0; off >>= 1) {
            #pragma unroll
            for (int p = 0; p < 4; ++p)
                accf[p] += __shfl_down_sync(0xffffffffu, accf[p], off);
        }
        if (l == 0) {
            #pragma unroll
            for (int p = 0; p < 4; ++p) sg[4 * w + p] = accf[p];
        }
        if (tid < 8) *(float4*)&sxp[tid * 4] = xw4;
        __syncthreads();

        // ---- gate nonlinearity + state update + tagged publish --------------
        if (tid < UPC) {
            int u = tid;
            // sxp layout is r = g*8+u packed as entries (tid*4..): remap:
            // sxp[e] holds W_ih gate-input for row e (e = g*8 + u)
            float gi = sg[u]      + sxp[u]      + sbias[u];
            float gf = sg[8 + u]  + sxp[8 + u]  + sbias[8 + u];
            float gg = sg[16 + u] + sxp[16 + u] + sbias[16 + u];
            float go = sg[24 + u] + sxp[24 + u] + sbias[24 + u];
            float iv = sigm(gi), fv = sigm(gf);
            float gv = tanh_acc(gg), ov = sigm(go);
            c_state = fv * c_state + iv * gv;
            float hval = ov * tanh_acc(c_state);
            stcg_u2(&g_hpub[step * HID + b * UPC + u],
                    __float_as_uint(hval), gen);
        }
        __syncthreads();
    }
}

// ======================= Kernel 3: classifier head ===========================
__global__ __launch_bounds__(256)
void out_kernel(const float* __restrict__ W_out, const float* __restrict__ b_out,
                float* __restrict__ out)
{
    __shared__ float sl[NCLS];
    __shared__ float s_lse;
    const int tid = threadIdx.x, wp_ = tid >> 5, lane = tid & 31;

    for (int ll = wp_; ll < NCLS; ll += 8) {
        float s = 0.0f;
        #pragma unroll 8
        for (int j = lane; j < HID; j += 32) {
            float hv = __uint_as_float(g_hpub[SEQ * HID + j].x);
            s = fmaf(hv, W_out[ll * HID + j], s);
        }
        #pragma unroll
        for (int off = 16; off > 0; off >>= 1)
            s += __shfl_down_sync(0xffffffffu, s, off);
        if (lane == 0) sl[ll] = s + b_out[ll];
    }
    __syncthreads();
    if (tid == 0) {
        float mx = -3.4e38f;
        for (int ll = 0; ll < NCLS; ++ll) mx = fmaxf(mx, sl[ll]);
        float se = 0.0f;
        for (int ll = 0; ll < NCLS; ++ll) se += __expf(sl[ll] - mx);
        s_lse = mx + __logf(se);
    }
    __syncthreads();
    if (tid < NCLS) out[tid] = sl[tid] - s_lse;
}

// ======================= launch ==============================================
extern "C" void kernel_launch(void* const* d_in, const int* in_sizes, int n_in,
                              void* d_out, int out_size) {
    const float* x     = (const float*)d_in[0];
    const float* h0    = (const float*)d_in[1];
    const float* c0    = (const float*)d_in[2];
    const float* cb    = (const float*)d_in[3];
    const float* W_ih  = (const float*)d_in[4];
    const float* W_hh  = (const float*)d_in[5];
    const float* b_ih  = (const float*)d_in[6];
    const float* b_hh  = (const float*)d_in[7];
    const float* W_out = (const float*)d_in[8];
    const float* b_out = (const float*)d_in[9];

    cudaFuncSetAttribute(vq_kernel, cudaFuncAttributeMaxDynamicSharedMemorySize,
                         (int)VQ_SMEM);

    vq_kernel<<<SEQ / VQ_TOK, TPB, VQ_SMEM>>>(x, cb);
    prep_kernel<<<(KCB * 4 * HID) / 256, 256>>>(W_ih);
    lstm_kernel<<<NCTA, TPB>>>(h0, c0, W_hh, b_ih, b_hh);
    out_kernel<<<1, 256>>>(W_out, b_out, (float*)d_out);
}

// round 5
// speedup vs baseline: 2.4273x; 1.0024x over previous
#include <cuda_runtime.h>
#include <cstdint>

#define SEQ   8192
#define DIM   256
#define HID   1024
#define KCB   512
#define NCLS  50
#define NCTA  128
#define TPB   256
#define UPC   8        // hidden units per CTA = HID / NCTA

// ---------------- device-global scratch (no allocations allowed) -------------
__device__ int      g_idx[SEQ];
// h publish buffer: slot s holds h(s), one {f32 bits, gen tag} per unit. 67 MB.
__device__ uint2    g_hpub[(SEQ + 1) * HID];
// W_ih transposed+permuted: [k][cta*32 + r] where r = gate*8 + unit. 8 MB.
__device__ float    g_wih_t[KCB * 4 * HID];
__device__ unsigned g_run = 0;   // generation counter, bumped once per launch

// ---------------- accurate-enough activations (fast-math independent) --------
__device__ __forceinline__ float sigm(float x) {
    return 1.0f / (1.0f + __expf(-x));
}
__device__ __forceinline__ float tanh_acc(float x) {
    float t = __expf(-2.0f * fabsf(x));
    float r = (1.0f - t) / (1.0f + t);
    return copysignf(r, x);
}

// packed f32x2 FMA (PTX-only pattern; element-wise fp32 FMA on a 64-bit pair)
__device__ __forceinline__ void ffma2(unsigned long long& d,
                                      unsigned long long a,
                                      unsigned long long b) {
    asm("fma.rn.f32x2 %0, %1, %2, %0;" : "+l"(d) : "l"(a), "l"(b));
}

__device__ __forceinline__ uint4 ldcg_u4(const uint4* p) {
    uint4 v;
    asm volatile("ld.global.cg.v4.u32 {%0,%1,%2,%3}, [%4];"
                 : "=r"(v.x), "=r"(v.y), "=r"(v.z), "=r"(v.w)
                 : "l"(p) : "memory");
    return v;
}
__device__ __forceinline__ void stcg_u2(uint2* p, unsigned a, unsigned b) {
    asm volatile("st.global.cg.v2.u32 [%0], {%1,%2};"
                 :: "l"(p), "r"(a), "r"(b) : "memory");
}

// ======================= Kernel 1: VQ assignment (unchanged) =================
#define VQ_TOK  32
#define VQ_TILE 32
#define VQ_PAD  260
#define VQ_SMEM ((VQ_TOK * VQ_PAD + VQ_TILE * VQ_PAD) * sizeof(float))

__global__ __launch_bounds__(TPB)
void vq_kernel(const float* __restrict__ x, const float* __restrict__ cb) {
    extern __shared__ float sm[];
    float* sx  = sm;
    float* scb = sm + VQ_TOK * VQ_PAD;
    __shared__ float scn[KCB];

    const int tid = threadIdx.x;
    const int t0  = blockIdx.x * VQ_TOK;

    for (int i = tid; i < VQ_TOK * (DIM / 4); i += TPB) {
        int tt = i >> 6, d4 = i & 63;
        float4 v = *(const float4*)&x[(t0 + tt) * DIM + d4 * 4];
        *(float4*)&sx[tt * VQ_PAD + d4 * 4] = v;
    }
    for (int k = tid; k < KCB; k += TPB) {
        float s0 = 0.f, s1 = 0.f, s2 = 0.f, s3 = 0.f;
        const float4* cr = (const float4*)&cb[k * DIM];
        #pragma unroll 8
        for (int d = 0; d < DIM / 4; ++d) {
            float4 v = cr[d];
            s0 = fmaf(v.x, v.x, s0); s1 = fmaf(v.y, v.y, s1);
            s2 = fmaf(v.z, v.z, s2); s3 = fmaf(v.w, v.w, s3);
        }
        scn[k] = (s0 + s1) + (s2 + s3);
    }
    __syncthreads();

    const int tt = tid >> 3;
    const int k0 = tid & 7;
    float best = 3.4e38f;
    int   bidx = 0;

    for (int tile = 0; tile < KCB / VQ_TILE; ++tile) {
        for (int i = tid; i < VQ_TILE * (DIM / 4); i += TPB) {
            int cc = i >> 6, d4 = i & 63;
            float4 v = *(const float4*)&cb[(tile * VQ_TILE + cc) * DIM + d4 * 4];
            *(float4*)&scb[cc * VQ_PAD + d4 * 4] = v;
        }
        __syncthreads();
        for (int c = k0; c < VQ_TILE; c += 8) {
            float a0 = 0.f, a1 = 0.f, a2 = 0.f, a3 = 0.f;
            const float* xr = &sx[tt * VQ_PAD];
            const float* cr = &scb[c * VQ_PAD];
            #pragma unroll
            for (int d = 0; d < DIM; d += 4) {
                float4 xv = *(const float4*)&xr[d];
                float4 cv = *(const float4*)&cr[d];
                a0 = fmaf(xv.x, cv.x, a0); a1 = fmaf(xv.y, cv.y, a1);
                a2 = fmaf(xv.z, cv.z, a2); a3 = fmaf(xv.w, cv.w, a3);
            }
            int   kk   = tile * VQ_TILE + c;
            float dist = scn[kk] - 2.0f * ((a0 + a1) + (a2 + a3));
            if (dist < best) { best = dist; bidx = kk; }
        }
        __syncthreads();
    }
    #pragma unroll
    for (int off = 4; off > 0; off >>= 1) {
        float ob = __shfl_down_sync(0xffffffffu, best, off, 8);
        int   oi = __shfl_down_sync(0xffffffffu, bidx, off, 8);
        if (ob < best || (ob == best && oi < bidx)) { best = ob; bidx = oi; }
    }
    if (k0 == 0) g_idx[t0 + tt] = bidx;
}

// ======================= Kernel 1b: prep (W_ih transpose + gen bump) =========
// g_wih_t[k*4096 + cta*32 + r] = W_ih[rowg(r,cta)*512 + k], rowg = g*1024+cta*8+u.
__global__ __launch_bounds__(256)
void prep_kernel(const float* __restrict__ W_ih) {
    int gid = blockIdx.x * 256 + threadIdx.x;       // 0 .. 512*4096-1
    if (gid == 0) g_run = g_run + 1;
    int k = gid >> 12;
    int c = gid & 4095;
    int r = c & 31, cta = c >> 5;
    int rowg = (r >> 3) * HID + cta * UPC + (r & 7);
    g_wih_t[gid] = __ldg(&W_ih[rowg * KCB + k]);
}

// ======================= Kernel 2: persistent data-flow LSTM =================
// 128 CTAs x 256 threads (grid <= 148 SMs -> all co-resident, no deadlock).
// NO global barrier: h published as {value, gen} 8-byte words, consumers poll
// with L1-bypassing loads. Warp w owns gate-rows 4w..4w+3; lane l owns h slice
// [32l, 32l+32). Weights live in registers as f32x2 pairs.
#define SH_STRIDE 36   // 32 + 4 pad floats -> conflict-free lane-strided reads

__global__ __launch_bounds__(TPB, 1)
void lstm_kernel(const float* __restrict__ h0,   const float* __restrict__ c0,
                 const float* __restrict__ W_hh,
                 const float* __restrict__ b_ih, const float* __restrict__ b_hh)
{
    __shared__ float sh[32 * SH_STRIDE];
    __shared__ float sg[32];
    __shared__ float sxp[32];
    __shared__ float sbias[32];
    __shared__ int   s_idx[2];

    const int tid  = threadIdx.x;
    const int b    = blockIdx.x;
    const int w    = tid >> 5;                // warp 0..7 -> rows 4w..4w+3
    const int l    = tid & 31;                // lane -> h slice [32l, 32l+32)
    const unsigned gen = g_run;

    // --- one-time: weights into registers as packed f32x2 pairs --------------
    unsigned long long wp[4][16];
    #pragma unroll
    for (int p = 0; p < 4; ++p) {
        int r    = 4 * w + p;
        int rowg = (r >> 3) * HID + b * UPC + (r & 7);
        const ulonglong2* wr = (const ulonglong2*)&W_hh[rowg * HID + l * 32];
        #pragma unroll
        for (int q = 0; q < 8; ++q) {
            ulonglong2 v = wr[q];
            wp[p][2 * q]     = v.x;
            wp[p][2 * q + 1] = v.y;
        }
    }
    if (tid < 32) {
        int rowg = (tid >> 3) * HID + b * UPC + (tid & 7);
        sbias[tid] = b_ih[rowg] + b_hh[rowg];
    }
    float c_state = 0.0f;
    if (tid < UPC) c_state = c0[b * UPC + tid];
    if (tid == 0)  s_idx[0] = g_idx[0];
    __syncthreads();

    for (int step = 1; step <= SEQ; ++step) {
        // ---- issue x-path loads early (independent of the recurrence) -------
        float4 xw4;
        if (tid < 8) {
            int idx = s_idx[(step - 1) & 1];
            xw4 = *(const float4*)&g_wih_t[idx * (4 * HID) + b * 32 + tid * 4];
        }
        if (tid == 8 && step < SEQ) s_idx[step & 1] = __ldg(&g_idx[step]);

        // ---- acquire h(step-1): input at step 1, else poll tagged publishes -
        float4 hv;
        if (step == 1) {
            hv = *(const float4*)&h0[tid * 4];
        } else {
            const uint4* pa = (const uint4*)&g_hpub[(step - 1) * HID + tid * 4];
            uint4 A, B;
            for (;;) {
                A = ldcg_u4(pa);
                B = ldcg_u4(pa + 1);
                if (A.y == gen && A.w == gen && B.y == gen && B.w == gen) break;
            }
            hv.x = __uint_as_float(A.x); hv.y = __uint_as_float(A.z);
            hv.z = __uint_as_float(B.x); hv.w = __uint_as_float(B.z);
        }
        // stage: entries tid*4..+3 -> chunk tid>>3, offset (tid&7)*4
        *(float4*)&sh[(tid >> 3) * SH_STRIDE + (tid & 7) * 4] = hv;
        __syncthreads();

        // ---- register-resident GEMV: 4 rows x 32-wide slice, f32x2 FMAs -----
        unsigned long long acc[4] = {0ull, 0ull, 0ull, 0ull};
        const ulonglong2* hp = (const ulonglong2*)&sh[l * SH_STRIDE];
        #pragma unroll
        for (int q = 0; q < 8; ++q) {
            ulonglong2 h2 = hp[q];
            #pragma unroll
            for (int p = 0; p < 4; ++p) {
                ffma2(acc[p], wp[p][2 * q],     h2.x);
                ffma2(acc[p], wp[p][2 * q + 1], h2.y);
            }
        }
        float accf[4];
        #pragma unroll
        for (int p = 0; p < 4; ++p) {
            float lo, hi;
            asm("mov.b64 {%0,%1}, %2;" : "=f"(lo), "=f"(hi) : "l"(acc[p]));
            accf[p] = lo + hi;
        }
        #pragma unroll
        for (int off = 16; off > 0; off >>= 1) {
            #pragma unroll
            for (int p = 0; p < 4; ++p)
                accf[p] += __shfl_down_sync(0xffffffffu, accf[p], off);
        }
        if (l == 0) {
            #pragma unroll
            for (int p = 0; p < 4; ++p) sg[4 * w + p] = accf[p];
        }
        if (tid < 8) *(float4*)&sxp[tid * 4] = xw4;
        __syncthreads();

        // ---- gate nonlinearity + state update + tagged publish --------------
        if (tid < UPC) {
            int u = tid;
            // sxp layout is r = g*8+u packed as entries (tid*4..): remap:
            // sxp[e] holds W_ih gate-input for row e (e = g*8 + u)
            float gi = sg[u]      + sxp[u]      + sbias[u];
            float gf = sg[8 + u]  + sxp[8 + u]  + sbias[8 + u];
            float gg = sg[16 + u] + sxp[16 + u] + sbias[16 + u];
            float go = sg[24 + u] + sxp[24 + u] + sbias[24 + u];
            float iv = sigm(gi), fv = sigm(gf);
            float gv = tanh_acc(gg), ov = sigm(go);
            c_state = fv * c_state + iv * gv;
            float hval = ov * tanh_acc(c_state);
            stcg_u2(&g_hpub[step * HID + b * UPC + u],
                    __float_as_uint(hval), gen);
        }
        __syncthreads();
    }
}

// ======================= Kernel 3: classifier head ===========================
__global__ __launch_bounds__(256)
void out_kernel(const float* __restrict__ W_out, const float* __restrict__ b_out,
                float* __restrict__ out)
{
    __shared__ float sl[NCLS];
    __shared__ float s_lse;
    const int tid = threadIdx.x, wp_ = tid >> 5, lane = tid & 31;

    for (int ll = wp_; ll < NCLS; ll += 8) {
        float s = 0.0f;
        #pragma unroll 8
        for (int j = lane; j < HID; j += 32) {
            float hv = __uint_as_float(g_hpub[SEQ * HID + j].x);
            s = fmaf(hv, W_out[ll * HID + j], s);
        }
        #pragma unroll
        for (int off = 16; off > 0; off >>= 1)
            s += __shfl_down_sync(0xffffffffu, s, off);
        if (lane == 0) sl[ll] = s + b_out[ll];
    }
    __syncthreads();
    if (tid == 0) {
        float mx = -3.4e38f;
        for (int ll = 0; ll < NCLS; ++ll) mx = fmaxf(mx, sl[ll]);
        float se = 0.0f;
        for (int ll = 0; ll < NCLS; ++ll) se += __expf(sl[ll] - mx);
        s_lse = mx + __logf(se);
    }
    __syncthreads();
    if (tid < NCLS) out[tid] = sl[tid] - s_lse;
}

// ======================= launch ==============================================
extern "C" void kernel_launch(void* const* d_in, const int* in_sizes, int n_in,
                              void* d_out, int out_size) {
    const float* x     = (const float*)d_in[0];
    const float* h0    = (const float*)d_in[1];
    const float* c0    = (const float*)d_in[2];
    const float* cb    = (const float*)d_in[3];
    const float* W_ih  = (const float*)d_in[4];
    const float* W_hh  = (const float*)d_in[5];
    const float* b_ih  = (const float*)d_in[6];
    const float* b_hh  = (const float*)d_in[7];
    const float* W_out = (const float*)d_in[8];
    const float* b_out = (const float*)d_in[9];

    cudaFuncSetAttribute(vq_kernel, cudaFuncAttributeMaxDynamicSharedMemorySize,
                         (int)VQ_SMEM);

    vq_kernel<<<SEQ / VQ_TOK, TPB, VQ_SMEM>>>(x, cb);
    prep_kernel<<<(KCB * 4 * HID) / 256, 256>>>(W_ih);
    lstm_kernel<<<NCTA, TPB>>>(h0, c0, W_hh, b_ih, b_hh);
    out_kernel<<<1, 256>>>(W_out, b_out, (float*)d_out);
}